// round 2
// baseline (speedup 1.0000x reference)
#include <cuda_runtime.h>

#define N_NODES 100000
#define N_EDGES 1600000
#define D 64
#define H 128

// Scratch aggregation buffer (device global — no allocation allowed)
__device__ float g_agg[N_NODES * D];

// ---------------------------------------------------------------------------
// Kernel 1: agg <- x   (self term, (1+eps)=1)
// ---------------------------------------------------------------------------
__global__ void init_agg_kernel(const float4* __restrict__ x) {
    int i = blockIdx.x * blockDim.x + threadIdx.x;
    if (i < N_NODES * D / 4) {
        reinterpret_cast<float4*>(g_agg)[i] = x[i];
    }
}

// ---------------------------------------------------------------------------
// Kernel 2: scatter-add  agg[dst] += x[src]  over all edges.
// 16 threads per edge, one float4 each. Vectorized float4 atomicAdd (sm_90+).
// edge_index is int32 (JAX x64 disabled -> int64 request yields int32).
// ---------------------------------------------------------------------------
__global__ void scatter_kernel(const float4* __restrict__ x,
                               const int* __restrict__ edge_index) {
    int gid = blockIdx.x * blockDim.x + threadIdx.x;   // 25.6M threads total
    if (gid >= N_EDGES * 16) return;
    int e = gid >> 4;
    int q = gid & 15;
    int src = edge_index[e];
    int dst = edge_index[N_EDGES + e];
    float4 v = __ldg(&x[(long long)src * (D / 4) + q]);
    atomicAdd(reinterpret_cast<float4*>(g_agg) + (long long)dst * (D / 4) + q, v);
}

// ---------------------------------------------------------------------------
// Kernel 3: fused MLP  out = relu(agg @ W1 + b1) @ W2 + b2
// One thread per node. Weights staged in dynamic smem:
//   sW1T[j][k] = W1[k][j]  (column of W1 contiguous -> broadcast LDS.128)
//   sW2 [j][k] = W2[j][k]  (row already contiguous)
// t[64] and y[64] live in registers as float4[16].
// ---------------------------------------------------------------------------
__global__ void __launch_bounds__(128) mlp_kernel(
    const float* __restrict__ W1, const float* __restrict__ b1,
    const float* __restrict__ W2, const float* __restrict__ b2,
    float* __restrict__ out)
{
    extern __shared__ float smem[];
    float* sW1T = smem;               // H*D floats
    float* sW2  = smem + H * D;       // H*D floats
    float* sB1  = smem + 2 * H * D;   // H floats
    float* sB2  = sB1 + H;            // D floats (offset 16-byte aligned)

    const int tid = threadIdx.x;

    // Stage W1 transposed: W1 is [D][H] row-major; write sW1T[j*D + k]
    for (int i = tid; i < D * H; i += 128) {
        int k = i / H;
        int j = i % H;
        sW1T[j * D + k] = W1[i];
    }
    // Stage W2 [H][D] as-is
    for (int i = tid; i < H * D; i += 128) {
        sW2[i] = W2[i];
    }
    if (tid < H) sB1[tid] = b1[tid];
    if (tid < D) sB2[tid] = b2[tid];
    __syncthreads();

    const int node = blockIdx.x * 128 + tid;
    if (node >= N_NODES) return;

    // Load this node's aggregated feature vector into registers
    float4 t[16];
    const float4* aggp = reinterpret_cast<const float4*>(g_agg) + node * 16;
    #pragma unroll
    for (int k = 0; k < 16; k++) t[k] = aggp[k];

    float4 y[16];
    #pragma unroll
    for (int k = 0; k < 16; k++) y[k] = make_float4(0.f, 0.f, 0.f, 0.f);

    const float4* sW1T4 = reinterpret_cast<const float4*>(sW1T);
    const float4* sW2_4 = reinterpret_cast<const float4*>(sW2);

    for (int j = 0; j < H; j++) {
        // dot(t, W1[:,j])  -- 4-wide partial accumulators for ILP
        float4 a = make_float4(0.f, 0.f, 0.f, 0.f);
        #pragma unroll
        for (int k = 0; k < 16; k++) {
            float4 w = sW1T4[j * 16 + k];   // uniform address -> broadcast
            a.x = fmaf(t[k].x, w.x, a.x);
            a.y = fmaf(t[k].y, w.y, a.y);
            a.z = fmaf(t[k].z, w.z, a.z);
            a.w = fmaf(t[k].w, w.w, a.w);
        }
        float h = (a.x + a.y) + (a.z + a.w) + sB1[j];
        h = fmaxf(h, 0.0f);
        // y += h * W2[j,:]
        #pragma unroll
        for (int k = 0; k < 16; k++) {
            float4 w = sW2_4[j * 16 + k];   // uniform address -> broadcast
            y[k].x = fmaf(h, w.x, y[k].x);
            y[k].y = fmaf(h, w.y, y[k].y);
            y[k].z = fmaf(h, w.z, y[k].z);
            y[k].w = fmaf(h, w.w, y[k].w);
        }
    }

    // out = y + b2
    float4* outp = reinterpret_cast<float4*>(out) + node * 16;
    const float4* sB2_4 = reinterpret_cast<const float4*>(sB2);
    #pragma unroll
    for (int k = 0; k < 16; k++) {
        float4 v = y[k];
        float4 b = sB2_4[k];
        v.x += b.x; v.y += b.y; v.z += b.z; v.w += b.w;
        outp[k] = v;
    }
}

// ---------------------------------------------------------------------------
extern "C" void kernel_launch(void* const* d_in, const int* in_sizes, int n_in,
                              void* d_out, int out_size) {
    const float* x  = (const float*)d_in[0];
    const int*   ei = (const int*)d_in[1];
    const float* W1 = (const float*)d_in[2];
    const float* b1 = (const float*)d_in[3];
    const float* W2 = (const float*)d_in[4];
    const float* b2 = (const float*)d_in[5];
    float* out = (float*)d_out;

    // 1) agg <- x
    {
        int n = N_NODES * D / 4;
        init_agg_kernel<<<(n + 255) / 256, 256>>>(
            reinterpret_cast<const float4*>(x));
    }

    // 2) scatter-add over edges
    {
        long long total = (long long)N_EDGES * 16;
        int blocks = (int)((total + 255) / 256);
        scatter_kernel<<<blocks, 256>>>(
            reinterpret_cast<const float4*>(x), ei);
    }

    // 3) fused MLP
    {
        size_t smem = (size_t)(2 * H * D + H + D) * sizeof(float);
        static bool attr_set = false;
        if (!attr_set) {
            cudaFuncSetAttribute(mlp_kernel,
                                 cudaFuncAttributeMaxDynamicSharedMemorySize,
                                 (int)smem);
            attr_set = true;
        }
        int blocks = (N_NODES + 127) / 128;
        mlp_kernel<<<blocks, 128, smem>>>(W1, b1, W2, b2, out);
    }
}

// round 3
// speedup vs baseline: 1.0161x; 1.0161x over previous
#include <cuda_runtime.h>

#define N_NODES 100000
#define N_EDGES 1600000
#define D 64
#define H 128

typedef unsigned long long u64;

// Scratch aggregation buffer (device global — no allocation allowed)
__device__ float g_agg[N_NODES * D];

// ---- packed fp32x2 helpers (Blackwell; ptxas never emits these from C++) ----
__device__ __forceinline__ u64 fma2(u64 a, u64 b, u64 c) {
    u64 d;
    asm("fma.rn.f32x2 %0, %1, %2, %3;" : "=l"(d) : "l"(a), "l"(b), "l"(c));
    return d;
}
__device__ __forceinline__ u64 add2(u64 a, u64 b) {
    u64 d;
    asm("add.rn.f32x2 %0, %1, %2;" : "=l"(d) : "l"(a), "l"(b));
    return d;
}
__device__ __forceinline__ float2 unpack2(u64 a) {
    float2 f;
    asm("mov.b64 {%0, %1}, %2;" : "=f"(f.x), "=f"(f.y) : "l"(a));
    return f;
}
__device__ __forceinline__ u64 pack2(float lo, float hi) {
    u64 d;
    asm("mov.b64 %0, {%1, %2};" : "=l"(d) : "f"(lo), "f"(hi));
    return d;
}

// ---------------------------------------------------------------------------
// Kernel 1: agg <- x   (self term, (1+eps)=1)
// ---------------------------------------------------------------------------
__global__ void init_agg_kernel(const float4* __restrict__ x) {
    int i = blockIdx.x * blockDim.x + threadIdx.x;
    if (i < N_NODES * D / 4) {
        reinterpret_cast<float4*>(g_agg)[i] = x[i];
    }
}

// ---------------------------------------------------------------------------
// Kernel 2: scatter-add  agg[dst] += x[src]  over all edges.
// 16 threads per edge, one float4 each. Vectorized float4 atomicAdd.
// edge_index is int32 (JAX x64 disabled -> int64 request yields int32).
// ---------------------------------------------------------------------------
__global__ void scatter_kernel(const float4* __restrict__ x,
                               const int* __restrict__ edge_index) {
    int gid = blockIdx.x * blockDim.x + threadIdx.x;   // 25.6M threads total
    if (gid >= N_EDGES * 16) return;
    int e = gid >> 4;
    int q = gid & 15;
    int src = edge_index[e];
    int dst = edge_index[N_EDGES + e];
    float4 v = __ldg(&x[(long long)src * (D / 4) + q]);
    atomicAdd(reinterpret_cast<float4*>(g_agg) + (long long)dst * (D / 4) + q, v);
}

// ---------------------------------------------------------------------------
// Kernel 3: fused MLP  out = relu(agg @ W1 + b1) @ W2 + b2
// One thread per node. All FMAs are packed fma.rn.f32x2 (2 FMA/issue).
// Weights staged in smem, read as uniform-address (broadcast) LDS.128:
//   sW1T[j][k] = W1[k][j]  (column of W1 contiguous)
//   sW2 [j][k] = W2[j][k]  (row already contiguous)
// ---------------------------------------------------------------------------
__global__ void __launch_bounds__(128) mlp_kernel(
    const float* __restrict__ W1, const float* __restrict__ b1,
    const float* __restrict__ W2, const float* __restrict__ b2,
    float* __restrict__ out)
{
    extern __shared__ float smem[];
    float* sW1T = smem;               // H*D floats
    float* sW2  = smem + H * D;       // H*D floats
    float* sB1  = smem + 2 * H * D;   // H floats
    float* sB2  = sB1 + H;            // D floats (16B aligned: 2*H*D+H multiple of 4)

    const int tid = threadIdx.x;

    // Stage W1 transposed: W1 is [D][H] row-major; write sW1T[j*D + k]
    for (int i = tid; i < D * H; i += 128) {
        int k = i / H;
        int j = i % H;
        sW1T[j * D + k] = W1[i];
    }
    // Stage W2 [H][D] as-is
    for (int i = tid; i < H * D; i += 128) {
        sW2[i] = W2[i];
    }
    if (tid < H) sB1[tid] = b1[tid];
    if (tid < D) sB2[tid] = b2[tid];
    __syncthreads();

    const int node = blockIdx.x * 128 + tid;
    if (node >= N_NODES) return;

    // Load this node's aggregated feature vector: 64 floats = 32 packed f32x2
    u64 t2[32];
    const ulonglong2* aggp =
        reinterpret_cast<const ulonglong2*>(g_agg) + (size_t)node * 16;
    #pragma unroll
    for (int k = 0; k < 16; k++) {
        ulonglong2 v = aggp[k];
        t2[2 * k]     = v.x;
        t2[2 * k + 1] = v.y;
    }

    u64 y2[32];
    #pragma unroll
    for (int k = 0; k < 32; k++) y2[k] = 0ULL;   // bits 0 == {0.0f, 0.0f}

    const ulonglong2* sW1T2 = reinterpret_cast<const ulonglong2*>(sW1T);
    const ulonglong2* sW2_2 = reinterpret_cast<const ulonglong2*>(sW2);

    for (int j = 0; j < H; j++) {
        // ---- layer 1: h_j = relu(dot(t, W1[:,j]) + b1[j]) ----
        u64 a0 = 0ULL, a1 = 0ULL, a2 = 0ULL, a3 = 0ULL;  // 4 indep chains
        #pragma unroll
        for (int k = 0; k < 8; k++) {
            ulonglong2 wA = sW1T2[j * 16 + 2 * k];       // broadcast LDS.128
            ulonglong2 wB = sW1T2[j * 16 + 2 * k + 1];
            a0 = fma2(t2[4 * k + 0], wA.x, a0);
            a1 = fma2(t2[4 * k + 1], wA.y, a1);
            a2 = fma2(t2[4 * k + 2], wB.x, a2);
            a3 = fma2(t2[4 * k + 3], wB.y, a3);
        }
        float2 f0 = unpack2(a0), f1 = unpack2(a1);
        float2 f2 = unpack2(a2), f3 = unpack2(a3);
        float h = ((f0.x + f0.y) + (f1.x + f1.y))
                + ((f2.x + f2.y) + (f3.x + f3.y)) + sB1[j];
        h = fmaxf(h, 0.0f);
        u64 hh = pack2(h, h);

        // ---- layer 2: y += h_j * W2[j,:] ----
        #pragma unroll
        for (int k = 0; k < 16; k++) {
            ulonglong2 w = sW2_2[j * 16 + k];            // broadcast LDS.128
            y2[2 * k]     = fma2(hh, w.x, y2[2 * k]);
            y2[2 * k + 1] = fma2(hh, w.y, y2[2 * k + 1]);
        }
    }

    // out = y + b2
    ulonglong2* outp = reinterpret_cast<ulonglong2*>(out) + (size_t)node * 16;
    const ulonglong2* sB2_2 = reinterpret_cast<const ulonglong2*>(sB2);
    #pragma unroll
    for (int k = 0; k < 16; k++) {
        ulonglong2 b = sB2_2[k];
        ulonglong2 v;
        v.x = add2(y2[2 * k], b.x);
        v.y = add2(y2[2 * k + 1], b.y);
        outp[k] = v;
    }
}

// ---------------------------------------------------------------------------
extern "C" void kernel_launch(void* const* d_in, const int* in_sizes, int n_in,
                              void* d_out, int out_size) {
    const float* x  = (const float*)d_in[0];
    const int*   ei = (const int*)d_in[1];
    const float* W1 = (const float*)d_in[2];
    const float* b1 = (const float*)d_in[3];
    const float* W2 = (const float*)d_in[4];
    const float* b2 = (const float*)d_in[5];
    float* out = (float*)d_out;

    // 1) agg <- x
    {
        int n = N_NODES * D / 4;
        init_agg_kernel<<<(n + 255) / 256, 256>>>(
            reinterpret_cast<const float4*>(x));
    }

    // 2) scatter-add over edges
    {
        long long total = (long long)N_EDGES * 16;
        int blocks = (int)((total + 255) / 256);
        scatter_kernel<<<blocks, 256>>>(
            reinterpret_cast<const float4*>(x), ei);
    }

    // 3) fused MLP
    {
        size_t smem = (size_t)(2 * H * D + H + D) * sizeof(float);
        static bool attr_set = false;
        if (!attr_set) {
            cudaFuncSetAttribute(mlp_kernel,
                                 cudaFuncAttributeMaxDynamicSharedMemorySize,
                                 (int)smem);
            attr_set = true;
        }
        int blocks = (N_NODES + 127) / 128;
        mlp_kernel<<<blocks, 128, smem>>>(W1, b1, W2, b2, out);
    }
}

// round 4
// speedup vs baseline: 1.0501x; 1.0335x over previous
#include <cuda_runtime.h>

#define N_NODES 100000
#define N_EDGES 1600000
#define D 64
#define H 128

#define SCAN_BLK 512
#define N_SCAN_BLKS ((N_NODES + SCAN_BLK - 1) / SCAN_BLK)   // 196

typedef unsigned long long u64;

// ---- device scratch (no allocation allowed) ----
__device__ float g_agg[N_NODES * D];
__device__ int   g_deg[N_NODES];
__device__ int   g_rowstart[N_NODES];   // exclusive scan of deg
__device__ int   g_cursor[N_NODES];     // running fill cursor
__device__ int   g_blocksum[N_SCAN_BLKS];
__device__ int   g_esrc[N_EDGES];       // src node per incoming-edge slot

// ---- packed fp32x2 helpers ----
__device__ __forceinline__ u64 fma2(u64 a, u64 b, u64 c) {
    u64 d;
    asm("fma.rn.f32x2 %0, %1, %2, %3;" : "=l"(d) : "l"(a), "l"(b), "l"(c));
    return d;
}
__device__ __forceinline__ u64 add2(u64 a, u64 b) {
    u64 d;
    asm("add.rn.f32x2 %0, %1, %2;" : "=l"(d) : "l"(a), "l"(b));
    return d;
}
__device__ __forceinline__ float2 unpack2(u64 a) {
    float2 f;
    asm("mov.b64 {%0, %1}, %2;" : "=f"(f.x), "=f"(f.y) : "l"(a));
    return f;
}
__device__ __forceinline__ u64 pack2(float lo, float hi) {
    u64 d;
    asm("mov.b64 %0, {%1, %2};" : "=l"(d) : "f"(lo), "f"(hi));
    return d;
}

// ===========================================================================
// CSR build
// ===========================================================================
__global__ void zero_deg_kernel() {
    int i = blockIdx.x * blockDim.x + threadIdx.x;
    if (i < N_NODES) g_deg[i] = 0;
}

__global__ void hist_kernel(const int* __restrict__ edge_index) {
    int e = blockIdx.x * blockDim.x + threadIdx.x;
    if (e < N_EDGES) atomicAdd(&g_deg[edge_index[N_EDGES + e]], 1);
}

// per-block exclusive scan of deg -> g_rowstart (partial), block totals -> g_blocksum
__global__ void scan1_kernel() {
    __shared__ int s[SCAN_BLK];
    int gid = blockIdx.x * SCAN_BLK + threadIdx.x;
    int v = (gid < N_NODES) ? g_deg[gid] : 0;
    s[threadIdx.x] = v;
    __syncthreads();
    #pragma unroll
    for (int off = 1; off < SCAN_BLK; off <<= 1) {
        int t = (threadIdx.x >= off) ? s[threadIdx.x - off] : 0;
        __syncthreads();
        s[threadIdx.x] += t;
        __syncthreads();
    }
    if (gid < N_NODES) g_rowstart[gid] = s[threadIdx.x] - v;   // exclusive
    if (threadIdx.x == SCAN_BLK - 1) g_blocksum[blockIdx.x] = s[SCAN_BLK - 1];
}

// single-block exclusive scan of block sums (196 values)
__global__ void scan2_kernel() {
    __shared__ int s[256];
    int tid = threadIdx.x;
    int v = (tid < N_SCAN_BLKS) ? g_blocksum[tid] : 0;
    s[tid] = v;
    __syncthreads();
    #pragma unroll
    for (int off = 1; off < 256; off <<= 1) {
        int t = (tid >= off) ? s[tid - off] : 0;
        __syncthreads();
        s[tid] += t;
        __syncthreads();
    }
    if (tid < N_SCAN_BLKS) g_blocksum[tid] = s[tid] - v;       // exclusive
}

// add block offsets; replicate to cursor
__global__ void scan3_kernel() {
    int gid = blockIdx.x * SCAN_BLK + threadIdx.x;
    if (gid < N_NODES) {
        int r = g_rowstart[gid] + g_blocksum[blockIdx.x];
        g_rowstart[gid] = r;
        g_cursor[gid]   = r;
    }
}

__global__ void fill_kernel(const int* __restrict__ edge_index) {
    int e = blockIdx.x * blockDim.x + threadIdx.x;
    if (e < N_EDGES) {
        int src = edge_index[e];
        int dst = edge_index[N_EDGES + e];
        int pos = atomicAdd(&g_cursor[dst], 1);
        g_esrc[pos] = src;
    }
}

// ===========================================================================
// Gather: one warp per node. Half-warp h handles neighbor i (i%2==h);
// lane q (0..15) owns float4 chunk q of the 64-float row.
// agg[node] = x[node] + sum_{neighbors} x[src]
// ===========================================================================
__global__ void __launch_bounds__(256) gather_kernel(const float4* __restrict__ x) {
    int warp = (blockIdx.x * 256 + threadIdx.x) >> 5;
    if (warp >= N_NODES) return;
    int lane = threadIdx.x & 31;
    int q = lane & 15;
    int h = lane >> 4;

    int start = g_rowstart[warp];
    int deg   = g_deg[warp];

    float4 acc = make_float4(0.f, 0.f, 0.f, 0.f);
    for (int i = h; i < deg; i += 2) {
        int src = __ldg(&g_esrc[start + i]);          // broadcast within half-warp
        float4 v = __ldg(&x[(size_t)src * 16 + q]);
        acc.x += v.x; acc.y += v.y; acc.z += v.z; acc.w += v.w;
    }
    // fold h=1 into h=0
    acc.x += __shfl_down_sync(0xffffffffu, acc.x, 16);
    acc.y += __shfl_down_sync(0xffffffffu, acc.y, 16);
    acc.z += __shfl_down_sync(0xffffffffu, acc.z, 16);
    acc.w += __shfl_down_sync(0xffffffffu, acc.w, 16);

    if (h == 0) {
        float4 self = __ldg(&x[(size_t)warp * 16 + q]);
        acc.x += self.x; acc.y += self.y; acc.z += self.z; acc.w += self.w;
        reinterpret_cast<float4*>(g_agg)[(size_t)warp * 16 + q] = acc;
    }
}

// ===========================================================================
// Fused MLP (unchanged from R3): out = relu(agg @ W1 + b1) @ W2 + b2
// ===========================================================================
__global__ void __launch_bounds__(128) mlp_kernel(
    const float* __restrict__ W1, const float* __restrict__ b1,
    const float* __restrict__ W2, const float* __restrict__ b2,
    float* __restrict__ out)
{
    extern __shared__ float smem[];
    float* sW1T = smem;               // H*D
    float* sW2  = smem + H * D;       // H*D
    float* sB1  = smem + 2 * H * D;   // H
    float* sB2  = sB1 + H;            // D

    const int tid = threadIdx.x;
    for (int i = tid; i < D * H; i += 128) {
        int k = i / H, j = i % H;
        sW1T[j * D + k] = W1[i];
    }
    for (int i = tid; i < H * D; i += 128) sW2[i] = W2[i];
    if (tid < H) sB1[tid] = b1[tid];
    if (tid < D) sB2[tid] = b2[tid];
    __syncthreads();

    const int node = blockIdx.x * 128 + tid;
    if (node >= N_NODES) return;

    u64 t2[32];
    const ulonglong2* aggp =
        reinterpret_cast<const ulonglong2*>(g_agg) + (size_t)node * 16;
    #pragma unroll
    for (int k = 0; k < 16; k++) {
        ulonglong2 v = aggp[k];
        t2[2 * k] = v.x;
        t2[2 * k + 1] = v.y;
    }

    u64 y2[32];
    #pragma unroll
    for (int k = 0; k < 32; k++) y2[k] = 0ULL;

    const ulonglong2* sW1T2 = reinterpret_cast<const ulonglong2*>(sW1T);
    const ulonglong2* sW2_2 = reinterpret_cast<const ulonglong2*>(sW2);

    for (int j = 0; j < H; j++) {
        u64 a0 = 0ULL, a1 = 0ULL, a2 = 0ULL, a3 = 0ULL;
        #pragma unroll
        for (int k = 0; k < 8; k++) {
            ulonglong2 wA = sW1T2[j * 16 + 2 * k];
            ulonglong2 wB = sW1T2[j * 16 + 2 * k + 1];
            a0 = fma2(t2[4 * k + 0], wA.x, a0);
            a1 = fma2(t2[4 * k + 1], wA.y, a1);
            a2 = fma2(t2[4 * k + 2], wB.x, a2);
            a3 = fma2(t2[4 * k + 3], wB.y, a3);
        }
        float2 f0 = unpack2(a0), f1 = unpack2(a1);
        float2 f2 = unpack2(a2), f3 = unpack2(a3);
        float hv = ((f0.x + f0.y) + (f1.x + f1.y))
                 + ((f2.x + f2.y) + (f3.x + f3.y)) + sB1[j];
        hv = fmaxf(hv, 0.0f);
        u64 hh = pack2(hv, hv);

        #pragma unroll
        for (int k = 0; k < 16; k++) {
            ulonglong2 w = sW2_2[j * 16 + k];
            y2[2 * k]     = fma2(hh, w.x, y2[2 * k]);
            y2[2 * k + 1] = fma2(hh, w.y, y2[2 * k + 1]);
        }
    }

    ulonglong2* outp = reinterpret_cast<ulonglong2*>(out) + (size_t)node * 16;
    const ulonglong2* sB2_2 = reinterpret_cast<const ulonglong2*>(sB2);
    #pragma unroll
    for (int k = 0; k < 16; k++) {
        ulonglong2 b = sB2_2[k];
        ulonglong2 v;
        v.x = add2(y2[2 * k], b.x);
        v.y = add2(y2[2 * k + 1], b.y);
        outp[k] = v;
    }
}

// ===========================================================================
extern "C" void kernel_launch(void* const* d_in, const int* in_sizes, int n_in,
                              void* d_out, int out_size) {
    const float* x  = (const float*)d_in[0];
    const int*   ei = (const int*)d_in[1];
    const float* W1 = (const float*)d_in[2];
    const float* b1 = (const float*)d_in[3];
    const float* W2 = (const float*)d_in[4];
    const float* b2 = (const float*)d_in[5];
    float* out = (float*)d_out;

    // CSR build
    zero_deg_kernel<<<(N_NODES + 255) / 256, 256>>>();
    hist_kernel<<<(N_EDGES + 255) / 256, 256>>>(ei);
    scan1_kernel<<<N_SCAN_BLKS, SCAN_BLK>>>();
    scan2_kernel<<<1, 256>>>();
    scan3_kernel<<<N_SCAN_BLKS, SCAN_BLK>>>();
    fill_kernel<<<(N_EDGES + 255) / 256, 256>>>(ei);

    // gather (fuses self term)
    {
        int warps = N_NODES;
        int blocks = (warps * 32 + 255) / 256;
        gather_kernel<<<blocks, 256>>>(reinterpret_cast<const float4*>(x));
    }

    // fused MLP
    {
        size_t smem = (size_t)(2 * H * D + H + D) * sizeof(float);
        static bool attr_set = false;
        if (!attr_set) {
            cudaFuncSetAttribute(mlp_kernel,
                                 cudaFuncAttributeMaxDynamicSharedMemorySize,
                                 (int)smem);
            attr_set = true;
        }
        mlp_kernel<<<(N_NODES + 127) / 128, 128, smem>>>(W1, b1, W2, b2, out);
    }
}